// round 6
// baseline (speedup 1.0000x reference)
#include <cuda_runtime.h>

// Problem constants (fixed: N=2048, B=2)
#define NN   2048
#define BB   2
#define EW   (NN + 1)            // 2049  (== 1 mod 4)
#define HXH  (NN - 1)            // 2047
#define HXW  (NN)                // 2048  (== 0 mod 4)
#define HYH  (NN)                // 2048
#define HYW  (NN - 1)            // 2047  (== 3 mod 4)
#define EN   (EW * EW)
#define HXN  (HXH * HXW)
#define HYN  (HYH * HYW)
#define CFLF 0.35f

#define KF0 (-11.0f / 6.0f)
#define KF1 (3.0f)
#define KF2 (-1.5f)
#define KF3 (1.0f / 3.0f)
#define KB0 (-1.0f / 3.0f)
#define KB1 (1.5f)
#define KB2 (-3.0f)
#define KB3 (11.0f / 6.0f)

struct MCoef {
    float M00, M01, M02, M03, M11, M20, M21, M22, M23;
};

__device__ __forceinline__ MCoef make_M(const float* sb, const float* sd, const float* sg) {
    float beta = *sb, delta = *sd, gamma = *sg;
    MCoef m;
    m.M00 = -0.25f * beta + 0.1f * gamma;
    m.M01 =  0.25f * beta + delta - 0.5f - 0.1f * gamma;
    m.M02 =  0.25f * beta - 0.1f * gamma;
    m.M03 = -0.25f * beta + 0.1f * gamma;
    m.M11 = -2.0f * delta;
    m.M20 =  0.25f * beta - 0.1f * gamma;
    m.M21 = -0.25f * beta + delta + 0.5f + 0.1f * gamma;
    m.M22 = -0.25f * beta - 0.1f * gamma;
    m.M23 =  0.25f * beta + 0.1f * gamma;
    return m;
}

// ---------------------------------------------------------------------------
// Warp-coalesced store of a 128-float row segment (4 floats per lane, lane
// stride 4). gi = this lane's first global index; gi & 3 is warp-uniform.
// Rotates values across lanes so the bulk is one aligned STG.128 per lane.
// Whole warp must participate (warp-uniform call site).
// ---------------------------------------------------------------------------
__device__ __forceinline__ void warp_store128(float* __restrict__ out, int gi,
                                              float v0, float v1, float v2, float v3)
{
    const unsigned FULL = 0xffffffffu;
    const int lane = threadIdx.x & 31;
    const int s = gi & 3;                    // warp-uniform skew
    if (s == 0) {
        float4 w; w.x = v0; w.y = v1; w.z = v2; w.w = v3;
        *reinterpret_cast<float4*>(out + gi) = w;
        return;
    }
    float n0 = __shfl_down_sync(FULL, v0, 1);
    float n1 = __shfl_down_sync(FULL, v1, 1);
    float n2 = __shfl_down_sync(FULL, v2, 1);
    if (s == 1) {            // h = 3
        if (lane < 31) {
            float4 w; w.x = v3; w.y = n0; w.z = n1; w.w = n2;
            *reinterpret_cast<float4*>(out + gi + 3) = w;
        }
        if (lane == 0)  { out[gi] = v0; out[gi + 1] = v1; out[gi + 2] = v2; }
        else if (lane == 31) { out[gi + 3] = v3; }
    } else if (s == 2) {     // h = 2
        if (lane < 31) {
            float4 w; w.x = v2; w.y = v3; w.z = n0; w.w = n1;
            *reinterpret_cast<float4*>(out + gi + 2) = w;
        }
        if (lane == 0)  { out[gi] = v0; out[gi + 1] = v1; }
        else if (lane == 31) { out[gi + 2] = v2; out[gi + 3] = v3; }
    } else {                 // s = 3, h = 1
        if (lane < 31) {
            float4 w; w.x = v1; w.y = v2; w.z = v3; w.w = n0;
            *reinterpret_cast<float4*>(out + gi + 1) = w;
        }
        if (lane == 0)  { out[gi] = v0; }
        else if (lane == 31) { out[gi + 1] = v1; out[gi + 2] = v2; out[gi + 3] = v3; }
    }
}

// ---------------------------------------------------------------------------
// Compile-time-skew window load: out[t] = buf[idx+t], requires (idx&3)==K.
// ---------------------------------------------------------------------------
template<int W, int K>
__device__ __forceinline__ void load_win_k(const float* __restrict__ buf, int idx,
                                           float* __restrict__ out)
{
    constexpr int NV = (W + K + 3) / 4;
    const float4* p = reinterpret_cast<const float4*>(buf + (idx - K));
    float f[NV * 4];
    #pragma unroll
    for (int t = 0; t < NV; t++)
        *reinterpret_cast<float4*>(f + 4 * t) = p[t];
    #pragma unroll
    for (int t = 0; t < W; t++) out[t] = f[t + K];
}

// ---------------------------------------------------------------------------
// Generic (boundary) amper point: returns s1 - s2 at (i,j).
// ---------------------------------------------------------------------------
__device__ float amper_point(const float* __restrict__ Hxb,
                             const float* __restrict__ Hyb,
                             int i, int j, const MCoef& m)
{
    float s1 = 0.0f, s2 = 0.0f;
    bool irow = (i >= 2 && i <= NN - 2);
    bool jcol = (j >= 2 && j <= NN - 2);

#define HYv(r, c) Hyb[(r) * HYW + (c)]
#define HXv(r, c) Hxb[(r) * HXW + (c)]
    if (irow && jcol) {
        s1 += m.M00 * HYv(i - 2, j - 2) + m.M20 * HYv(i - 2, j);
        s1 += m.M01 * HYv(i - 1, j - 2) + m.M11 * HYv(i - 1, j - 1) + m.M21 * HYv(i - 1, j);
        s1 += m.M02 * HYv(i,     j - 2) + m.M22 * HYv(i,     j);
        s1 += m.M03 * HYv(i + 1, j - 2) + m.M23 * HYv(i + 1, j);
        s2 += m.M00 * HXv(i - 2, j - 2) + m.M01 * HXv(i - 2, j - 1)
            + m.M02 * HXv(i - 2, j)     + m.M03 * HXv(i - 2, j + 1);
        s2 += m.M11 * HXv(i - 1, j - 1);
        s2 += m.M20 * HXv(i,     j - 2) + m.M21 * HXv(i,     j - 1)
            + m.M22 * HXv(i,     j)     + m.M23 * HXv(i,     j + 1);
    }
    if (i >= 1 && j <= NN - 5) {
        s1 += KF0 * HYv(i - 1, j)     + KF1 * HYv(i - 1, j + 1)
            + KF2 * HYv(i - 1, j + 2) + KF3 * HYv(i - 1, j + 3);
    }
    if (i <= NN - 1 && j >= 5) {
        s1 += KB0 * HYv(i, j - 5) + KB1 * HYv(i, j - 4)
            + KB2 * HYv(i, j - 3) + KB3 * HYv(i, j - 2);
    }
    if (irow && j >= 1 && j <= 2) {
        s1 += -HYv(i - 1, j - 1) + 3.0f * HYv(i - 1, j)
              - 3.0f * HYv(i - 1, j + 1) + HYv(i - 1, j + 2);
    }
    if (irow && j >= NN - 2 && j <= NN - 1) {
        s1 += HYv(i, j - 4) - 3.0f * HYv(i, j - 3)
            + 3.0f * HYv(i, j - 2) - HYv(i, j - 1);
    }
    if (j >= 1 && i <= NN - 5) {
        s2 += KF0 * HXv(i, j - 1)     + KF1 * HXv(i + 1, j - 1)
            + KF2 * HXv(i + 2, j - 1) + KF3 * HXv(i + 3, j - 1);
    }
    if (j <= NN - 1 && i >= 5) {
        s2 += KB0 * HXv(i - 5, j) + KB1 * HXv(i - 4, j)
            + KB2 * HXv(i - 3, j) + KB3 * HXv(i - 2, j);
    }
    if (jcol && i >= 1 && i <= 2) {
        s2 += -HXv(i - 1, j - 1) + 3.0f * HXv(i, j - 1)
              - 3.0f * HXv(i + 1, j - 1) + HXv(i + 2, j - 1);
    }
    if (jcol && i >= NN - 2 && i <= NN - 1) {
        s2 += HXv(i - 4, j) - 3.0f * HXv(i - 3, j)
            + 3.0f * HXv(i - 2, j) - HXv(i - 1, j);
    }
#undef HYv
#undef HXv
    return s1 - s2;
}

// ---------------------------------------------------------------------------
// Amper Hy section (rows i0-2 .. i0+2). KY = skew of base window.
// ---------------------------------------------------------------------------
template<int KY>
__device__ __forceinline__ void amper_hy_sec(const float* __restrict__ hy, int base,
                                             const MCoef& m, float cM21KF0, float cM02KB3,
                                             float* __restrict__ s1a, float* __restrict__ s1b)
{
    float Y0[6], Y1[9], Y2[12], Y3[9], Y4[6];
    load_win_k<6,  KY          >(hy, base, Y0);
    load_win_k<9,  (KY + 3) & 3>(hy, base + HYW, Y1);
    load_win_k<12, (KY + 3) & 3>(hy, base + 2 * HYW - 3, Y2);
    load_win_k<9,  (KY + 2) & 3>(hy, base + 3 * HYW - 3, Y3);
    load_win_k<6,  KY          >(hy, base + 4 * HYW, Y4);

    #pragma unroll
    for (int q = 0; q < 4; q++) {
        s1a[q] += m.M00 * Y0[q] + m.M20 * Y0[q + 2];
        s1a[q] += m.M01 * Y1[q] + m.M11 * Y1[q + 1] + cM21KF0 * Y1[q + 2]
                + KF1 * Y1[q + 3] + KF2 * Y1[q + 4] + KF3 * Y1[q + 5];
        s1b[q] += m.M00 * Y1[q] + m.M20 * Y1[q + 2];
        s1a[q] += KB0 * Y2[q] + KB1 * Y2[q + 1] + KB2 * Y2[q + 2]
                + cM02KB3 * Y2[q + 3] + m.M22 * Y2[q + 5];
        s1b[q] += m.M01 * Y2[q + 3] + m.M11 * Y2[q + 4] + cM21KF0 * Y2[q + 5]
                + KF1 * Y2[q + 6] + KF2 * Y2[q + 7] + KF3 * Y2[q + 8];
        s1a[q] += m.M03 * Y3[q + 3] + m.M23 * Y3[q + 5];
        s1b[q] += KB0 * Y3[q] + KB1 * Y3[q + 1] + KB2 * Y3[q + 2]
                + cM02KB3 * Y3[q + 3] + m.M22 * Y3[q + 5];
        s1b[q] += m.M03 * Y4[q] + m.M23 * Y4[q + 2];
    }
}

// ---------------------------------------------------------------------------
// Amper Hx section (rows i0-5 .. i0+4). KX = skew of base window.
// ---------------------------------------------------------------------------
template<int KX>
__device__ __forceinline__ void amper_hx_sec(const float* __restrict__ hx, int base,
                                             const MCoef& m, float cM21KF0, float cM02KB3,
                                             float* __restrict__ s2a, float* __restrict__ s2b)
{
    float X0[4], X1[4], X2[4], X3[7], X4[7], X5[7], X6[7], X7[4], X8[4], X9[4];
    load_win_k<4, KX          >(hx, base, X0);
    load_win_k<4, KX          >(hx, base + HXW, X1);
    load_win_k<4, KX          >(hx, base + 2 * HXW, X2);
    load_win_k<7, (KX + 2) & 3>(hx, base + 3 * HXW - 2, X3);
    load_win_k<7, (KX + 2) & 3>(hx, base + 4 * HXW - 2, X4);
    load_win_k<7, (KX + 2) & 3>(hx, base + 5 * HXW - 2, X5);
    load_win_k<7, (KX + 2) & 3>(hx, base + 6 * HXW - 2, X6);
    load_win_k<4, (KX + 3) & 3>(hx, base + 7 * HXW - 1, X7);
    load_win_k<4, (KX + 3) & 3>(hx, base + 8 * HXW - 1, X8);
    load_win_k<4, (KX + 3) & 3>(hx, base + 9 * HXW - 1, X9);

    #pragma unroll
    for (int q = 0; q < 4; q++) {
        s2a[q] += KB0 * X0[q] + KB1 * X1[q] + KB2 * X2[q];
        s2b[q] += KB0 * X1[q] + KB1 * X2[q];
        s2a[q] += m.M00 * X3[q] + m.M01 * X3[q + 1] + cM02KB3 * X3[q + 2] + m.M03 * X3[q + 3];
        s2b[q] += KB2 * X3[q + 2];
        s2a[q] += m.M11 * X4[q + 1];
        s2b[q] += m.M00 * X4[q] + m.M01 * X4[q + 1] + cM02KB3 * X4[q + 2] + m.M03 * X4[q + 3];
        s2a[q] += m.M20 * X5[q] + cM21KF0 * X5[q + 1] + m.M22 * X5[q + 2] + m.M23 * X5[q + 3];
        s2b[q] += m.M11 * X5[q + 1];
        s2a[q] += KF1 * X6[q + 1];
        s2b[q] += m.M20 * X6[q] + cM21KF0 * X6[q + 1] + m.M22 * X6[q + 2] + m.M23 * X6[q + 3];
        s2a[q] += KF2 * X7[q] + KF3 * X8[q];
        s2b[q] += KF1 * X7[q] + KF2 * X8[q] + KF3 * X9[q];
    }
}

// ---------------------------------------------------------------------------
// Amper fast-path compute: produces final output values w0[4] (row i0) and
// w1[4] (row i0+1).
// ---------------------------------------------------------------------------
__device__ __forceinline__ void amper_fast_compute(
    const float* __restrict__ e_base, int eidx,
    const float* __restrict__ hy_base, int ybase,
    const float* __restrict__ hx_base, int xbase,
    const MCoef& m, float* __restrict__ w0, float* __restrict__ w1)
{
    const float cM21KF0 = m.M21 + KF0;
    const float cM02KB3 = m.M02 + KB3;
    float s1a[4] = {0, 0, 0, 0}, s1b[4] = {0, 0, 0, 0};
    float s2a[4] = {0, 0, 0, 0}, s2b[4] = {0, 0, 0, 0};

    float E0[4], E1[4];
    switch (eidx & 3) {   // EW == 1 mod 4
        case 0: load_win_k<4, 0>(e_base, eidx, E0); load_win_k<4, 1>(e_base, eidx + EW, E1); break;
        case 1: load_win_k<4, 1>(e_base, eidx, E0); load_win_k<4, 2>(e_base, eidx + EW, E1); break;
        case 2: load_win_k<4, 2>(e_base, eidx, E0); load_win_k<4, 3>(e_base, eidx + EW, E1); break;
        case 3: load_win_k<4, 3>(e_base, eidx, E0); load_win_k<4, 0>(e_base, eidx + EW, E1); break;
    }
    switch (ybase & 3) {
        case 0: amper_hy_sec<0>(hy_base, ybase, m, cM21KF0, cM02KB3, s1a, s1b); break;
        case 1: amper_hy_sec<1>(hy_base, ybase, m, cM21KF0, cM02KB3, s1a, s1b); break;
        case 2: amper_hy_sec<2>(hy_base, ybase, m, cM21KF0, cM02KB3, s1a, s1b); break;
        case 3: amper_hy_sec<3>(hy_base, ybase, m, cM21KF0, cM02KB3, s1a, s1b); break;
    }
    switch (xbase & 3) {
        case 0: amper_hx_sec<0>(hx_base, xbase, m, cM21KF0, cM02KB3, s2a, s2b); break;
        case 1: amper_hx_sec<1>(hx_base, xbase, m, cM21KF0, cM02KB3, s2a, s2b); break;
        case 2: amper_hx_sec<2>(hx_base, xbase, m, cM21KF0, cM02KB3, s2a, s2b); break;
        case 3: amper_hx_sec<3>(hx_base, xbase, m, cM21KF0, cM02KB3, s2a, s2b); break;
    }
    #pragma unroll
    for (int q = 0; q < 4; q++) {
        w0[q] = E0[q] + CFLF * (s1a[q] - s2a[q]);
        w1[q] = E1[q] + CFLF * (s1b[q] - s2b[q]);
    }
}

// ---------------------------------------------------------------------------
// Amper: 2 output rows x 4 cols per thread; 3-tier dispatch.
// ---------------------------------------------------------------------------
__global__ __launch_bounds__(128, 9)
void k_amper(const float* __restrict__ e_base,  int e_off,
             const float* __restrict__ hx_base, int hx_off,
             const float* __restrict__ hy_base, int hy_off,
             float* __restrict__ out_base,      int eo_off,
             const float* __restrict__ sb,
             const float* __restrict__ sd,
             const float* __restrict__ sg)
{
    int t  = blockIdx.x * 32 + threadIdx.x;
    int i0 = (blockIdx.y * blockDim.y + threadIdx.y) * 2;
    if (i0 > NN) return;                      // warp-uniform (y uniform in warp)
    int b = blockIdx.z;

    const int erow0 = eo_off + b * EN + i0 * EW;
    const int s = erow0 & 3;
    const int j = 4 * t - s;
    const bool valid = (j + 3 >= 0) && (j <= NN);

    MCoef m = make_M(sb, sd, sg);
    const int xb = hx_off + b * HXN;
    const int yb = hy_off + b * HYN;

    const bool th_fast = valid && (i0 >= 5) && (i0 <= NN - 6) && (j >= 5) && (j <= NN - 8);
    const unsigned bal = __ballot_sync(0xffffffffu, th_fast);

    if (bal == 0xffffffffu) {
        float w0[4], w1[4];
        amper_fast_compute(e_base, e_off + b * EN + i0 * EW + j,
                           hy_base, yb + (i0 - 2) * HYW + (j - 2),
                           hx_base, xb + (i0 - 5) * HXW + j, m, w0, w1);
        float4 w; w.x = w0[0]; w.y = w0[1]; w.z = w0[2]; w.w = w0[3];
        *reinterpret_cast<float4*>(out_base + erow0 + j) = w;     // aligned
        warp_store128(out_base, erow0 + EW + j, w1[0], w1[1], w1[2], w1[3]);
    } else if (th_fast) {
        float w0[4], w1[4];
        amper_fast_compute(e_base, e_off + b * EN + i0 * EW + j,
                           hy_base, yb + (i0 - 2) * HYW + (j - 2),
                           hx_base, xb + (i0 - 5) * HXW + j, m, w0, w1);
        float4 w; w.x = w0[0]; w.y = w0[1]; w.z = w0[2]; w.w = w0[3];
        *reinterpret_cast<float4*>(out_base + erow0 + j) = w;     // aligned
        float* p1 = out_base + erow0 + EW + j;
        #pragma unroll
        for (int q = 0; q < 4; q++) p1[q] = w1[q];
    } else if (valid) {
        const float* Eb  = e_base + e_off + b * EN;
        const float* Hxb = hx_base + xb;
        const float* Hyb = hy_base + yb;
        float* Eob = out_base + eo_off + b * EN;
        #pragma unroll
        for (int r = 0; r < 2; r++) {
            int ii = i0 + r;
            if (ii > NN) continue;
            #pragma unroll
            for (int q = 0; q < 4; q++) {
                int jj = j + q;
                if (jj < 0 || jj > NN) continue;
                float d = amper_point(Hxb, Hyb, ii, jj, m);
                Eob[ii * EW + jj] = Eb[ii * EW + jj] + CFLF * d;
            }
        }
    }
}

// ---------------------------------------------------------------------------
// Generic faraday point helpers
// ---------------------------------------------------------------------------
__device__ float faraday_s3(const float* __restrict__ Eb, int i, int j, const MCoef& m)
{
#define Ev(r, c) Eb[(r) * EW + (c)]
    float s3 = 0.0f;
    if (j >= 1 && j <= NN - 2) {
        s3 += m.M00 * Ev(i,     j - 1) + m.M01 * Ev(i,     j)
            + m.M02 * Ev(i,     j + 1) + m.M03 * Ev(i,     j + 2);
        s3 += m.M11 * Ev(i + 1, j);
        s3 += m.M20 * Ev(i + 2, j - 1) + m.M21 * Ev(i + 2, j)
            + m.M22 * Ev(i + 2, j + 1) + m.M23 * Ev(i + 2, j + 2);
    }
    if (i <= NN - 4)
        s3 += -1.5f * Ev(i + 1, j) + 2.0f * Ev(i + 2, j) - 0.5f * Ev(i + 3, j);
    if (i >= 2)
        s3 += 0.5f * Ev(i - 1, j + 1) - 2.0f * Ev(i, j + 1) + 1.5f * Ev(i + 1, j + 1);
#undef Ev
    return s3;
}

__device__ float faraday_s4(const float* __restrict__ Eb, int i, int j, const MCoef& m)
{
#define Ev(r, c) Eb[(r) * EW + (c)]
    float s4 = 0.0f;
    if (i >= 1 && i <= NN - 2) {
        s4 += m.M00 * Ev(i - 1, j) + m.M20 * Ev(i - 1, j + 2);
        s4 += m.M01 * Ev(i,     j) + m.M11 * Ev(i, j + 1) + m.M21 * Ev(i, j + 2);
        s4 += m.M02 * Ev(i + 1, j) + m.M22 * Ev(i + 1, j + 2);
        s4 += m.M03 * Ev(i + 2, j) + m.M23 * Ev(i + 2, j + 2);
    }
    if (j <= NN - 4)
        s4 += -1.5f * Ev(i, j + 1) + 2.0f * Ev(i, j + 2) - 0.5f * Ev(i, j + 3);
    if (j >= 2)
        s4 += 0.5f * Ev(i + 1, j - 1) - 2.0f * Ev(i + 1, j) + 1.5f * Ev(i + 1, j + 1);
#undef Ev
    return s4;
}

// ---------------------------------------------------------------------------
// Faraday E section (rows i0-1 .. i0+4). KE = skew of base window.
// ---------------------------------------------------------------------------
template<int KE>
__device__ __forceinline__ void faraday_e_sec(const float* __restrict__ e, int base,
                                              const MCoef& m, float cA, float cB, float cC,
                                              float* __restrict__ s3a, float* __restrict__ s3b,
                                              float* __restrict__ s4a, float* __restrict__ s4b)
{
    float W0[6], W1[8], W2[8], W3[7], W4[7], W5[4];
    load_win_k<6, KE          >(e, base, W0);
    load_win_k<8, KE          >(e, base + EW - 1, W1);
    load_win_k<8, (KE + 1) & 3>(e, base + 2 * EW - 1, W2);
    load_win_k<7, (KE + 2) & 3>(e, base + 3 * EW - 1, W3);
    load_win_k<7, (KE + 3) & 3>(e, base + 4 * EW - 1, W4);
    load_win_k<4, (KE + 1) & 3>(e, base + 5 * EW, W5);

    #pragma unroll
    for (int q = 0; q < 4; q++) {
        s3a[q] += 0.5f * W0[q + 1];
        s4a[q] += m.M00 * W0[q] + m.M20 * W0[q + 2];
        s3a[q] += m.M00 * W1[q] + m.M01 * W1[q + 1] + cA * W1[q + 2] + m.M03 * W1[q + 3];
        s4a[q] += m.M01 * W1[q + 1] + cB * W1[q + 2] + cC * W1[q + 3] - 0.5f * W1[q + 4];
        s3b[q] += 0.5f * W1[q + 2];
        s4b[q] += m.M00 * W1[q + 1] + m.M20 * W1[q + 3];
        s3a[q] += cB * W2[q + 1] + 1.5f * W2[q + 2];
        s4a[q] += 0.5f * W2[q] + cA * W2[q + 1] + 1.5f * W2[q + 2] + m.M22 * W2[q + 3];
        s3b[q] += m.M00 * W2[q] + m.M01 * W2[q + 1] + cA * W2[q + 2] + m.M03 * W2[q + 3];
        s4b[q] += m.M01 * W2[q + 1] + cB * W2[q + 2] + cC * W2[q + 3] - 0.5f * W2[q + 4];
        s3a[q] += m.M20 * W3[q] + cC * W3[q + 1] + m.M22 * W3[q + 2] + m.M23 * W3[q + 3];
        s4a[q] += m.M03 * W3[q + 1] + m.M23 * W3[q + 3];
        s3b[q] += cB * W3[q + 1] + 1.5f * W3[q + 2];
        s4b[q] += 0.5f * W3[q] + cA * W3[q + 1] + 1.5f * W3[q + 2] + m.M22 * W3[q + 3];
        s3a[q] += -0.5f * W4[q + 1];
        s3b[q] += m.M20 * W4[q] + cC * W4[q + 1] + m.M22 * W4[q + 2] + m.M23 * W4[q + 3];
        s4b[q] += m.M03 * W4[q + 1] + m.M23 * W4[q + 3];
        s3b[q] += -0.5f * W5[q];
    }
}

// ---------------------------------------------------------------------------
// Faraday fast-path compute: produces Hx outputs wx0/wx1 and Hy outputs
// wy0/wy1 (4 each).
// ---------------------------------------------------------------------------
__device__ __forceinline__ void faraday_fast_compute(
    const float* __restrict__ e_base, int ebase,
    const float* __restrict__ hx_base, int hxidx,
    const float* __restrict__ hy_base, int hyidx,
    const MCoef& m,
    float* __restrict__ wx0, float* __restrict__ wx1,
    float* __restrict__ wy0, float* __restrict__ wy1)
{
    const float cA = m.M02 - 2.0f;
    const float cB = m.M11 - 1.5f;
    const float cC = m.M21 + 2.0f;
    float s3a[4] = {0, 0, 0, 0}, s3b[4] = {0, 0, 0, 0};
    float s4a[4] = {0, 0, 0, 0}, s4b[4] = {0, 0, 0, 0};

    float hx0[4], hx1[4], hy0[4], hy1[4];
    switch (hxidx & 3) {         // HXW == 0 mod 4
        case 0: load_win_k<4, 0>(hx_base, hxidx, hx0); load_win_k<4, 0>(hx_base, hxidx + HXW, hx1); break;
        case 1: load_win_k<4, 1>(hx_base, hxidx, hx0); load_win_k<4, 1>(hx_base, hxidx + HXW, hx1); break;
        case 2: load_win_k<4, 2>(hx_base, hxidx, hx0); load_win_k<4, 2>(hx_base, hxidx + HXW, hx1); break;
        case 3: load_win_k<4, 3>(hx_base, hxidx, hx0); load_win_k<4, 3>(hx_base, hxidx + HXW, hx1); break;
    }
    switch (hyidx & 3) {         // HYW == 3 mod 4
        case 0: load_win_k<4, 0>(hy_base, hyidx, hy0); load_win_k<4, 3>(hy_base, hyidx + HYW, hy1); break;
        case 1: load_win_k<4, 1>(hy_base, hyidx, hy0); load_win_k<4, 0>(hy_base, hyidx + HYW, hy1); break;
        case 2: load_win_k<4, 2>(hy_base, hyidx, hy0); load_win_k<4, 1>(hy_base, hyidx + HYW, hy1); break;
        case 3: load_win_k<4, 3>(hy_base, hyidx, hy0); load_win_k<4, 2>(hy_base, hyidx + HYW, hy1); break;
    }
    switch (ebase & 3) {
        case 0: faraday_e_sec<0>(e_base, ebase, m, cA, cB, cC, s3a, s3b, s4a, s4b); break;
        case 1: faraday_e_sec<1>(e_base, ebase, m, cA, cB, cC, s3a, s3b, s4a, s4b); break;
        case 2: faraday_e_sec<2>(e_base, ebase, m, cA, cB, cC, s3a, s3b, s4a, s4b); break;
        case 3: faraday_e_sec<3>(e_base, ebase, m, cA, cB, cC, s3a, s3b, s4a, s4b); break;
    }
    #pragma unroll
    for (int q = 0; q < 4; q++) {
        wx0[q] = hx0[q] - CFLF * s3a[q];
        wx1[q] = hx1[q] - CFLF * s3b[q];
        wy0[q] = hy0[q] + CFLF * s4a[q];
        wy1[q] = hy1[q] + CFLF * s4b[q];
    }
}

// ---------------------------------------------------------------------------
// Fused faraday: 2 output rows x 4 cols per thread; 3-tier dispatch.
// ---------------------------------------------------------------------------
__global__ __launch_bounds__(128, 9)
void k_faraday(const float* __restrict__ e_base,  int e_off,
               const float* __restrict__ hx_base, int hx_off,
               const float* __restrict__ hy_base, int hy_off,
               float* __restrict__ out_base,      int hxo_off, int hyo_off,
               const float* __restrict__ sb,
               const float* __restrict__ sd,
               const float* __restrict__ sg)
{
    int t  = blockIdx.x * 32 + threadIdx.x;
    int i0 = (blockIdx.y * blockDim.y + threadIdx.y) * 2;
    if (i0 >= NN) return;                     // warp-uniform
    int b = blockIdx.z;

    const int sF = hxo_off & 3;
    const int j = 4 * t - sF;
    const bool valid = (j + 3 >= 0) && (j < NN);

    MCoef m = make_M(sb, sd, sg);
    const int eb = e_off + b * EN;
    const int xb = hx_off + b * HXN;
    const int yb = hy_off + b * HYN;

    const bool th_fast = valid && (i0 >= 2) && (i0 <= NN - 5) && (j >= 2) && (j <= NN - 7);
    const unsigned bal = __ballot_sync(0xffffffffu, th_fast);

    if (bal == 0xffffffffu) {
        float wx0[4], wx1[4], wy0[4], wy1[4];
        faraday_fast_compute(e_base, eb + (i0 - 1) * EW + j,
                             hx_base, xb + i0 * HXW + j,
                             hy_base, yb + i0 * HYW + j,
                             m, wx0, wx1, wy0, wy1);
        float4 w;
        w.x = wx0[0]; w.y = wx0[1]; w.z = wx0[2]; w.w = wx0[3];
        *reinterpret_cast<float4*>(out_base + hxo_off + b * HXN + i0 * HXW + j) = w;
        w.x = wx1[0]; w.y = wx1[1]; w.z = wx1[2]; w.w = wx1[3];
        *reinterpret_cast<float4*>(out_base + hxo_off + b * HXN + (i0 + 1) * HXW + j) = w;
        warp_store128(out_base, hyo_off + b * HYN + i0 * HYW + j,
                      wy0[0], wy0[1], wy0[2], wy0[3]);
        warp_store128(out_base, hyo_off + b * HYN + (i0 + 1) * HYW + j,
                      wy1[0], wy1[1], wy1[2], wy1[3]);
    } else if (th_fast) {
        float wx0[4], wx1[4], wy0[4], wy1[4];
        faraday_fast_compute(e_base, eb + (i0 - 1) * EW + j,
                             hx_base, xb + i0 * HXW + j,
                             hy_base, yb + i0 * HYW + j,
                             m, wx0, wx1, wy0, wy1);
        float4 w;
        w.x = wx0[0]; w.y = wx0[1]; w.z = wx0[2]; w.w = wx0[3];
        *reinterpret_cast<float4*>(out_base + hxo_off + b * HXN + i0 * HXW + j) = w;
        w.x = wx1[0]; w.y = wx1[1]; w.z = wx1[2]; w.w = wx1[3];
        *reinterpret_cast<float4*>(out_base + hxo_off + b * HXN + (i0 + 1) * HXW + j) = w;
        float* hyw0 = out_base + hyo_off + b * HYN + i0 * HYW + j;
        float* hyw1 = hyw0 + HYW;
        #pragma unroll
        for (int q = 0; q < 4; q++) {
            hyw0[q] = wy0[q];
            hyw1[q] = wy1[q];
        }
    } else if (valid) {
        const float* Eb  = e_base + eb;
        const float* Hxb = hx_base + xb;
        const float* Hyb = hy_base + yb;
        float* Hxob = out_base + hxo_off + b * HXN;
        float* Hyob = out_base + hyo_off + b * HYN;
        #pragma unroll
        for (int r = 0; r < 2; r++) {
            int ii = i0 + r;
            if (ii >= NN) continue;
            #pragma unroll
            for (int q = 0; q < 4; q++) {
                int jj = j + q;
                if (jj < 0 || jj >= NN) continue;
                if (ii < HXH && jj < HXW) {
                    float s3 = faraday_s3(Eb, ii, jj, m);
                    Hxob[ii * HXW + jj] = Hxb[ii * HXW + jj] - CFLF * s3;
                }
                if (ii < HYH && jj < HYW) {
                    float s4 = faraday_s4(Eb, ii, jj, m);
                    Hyob[ii * HYW + jj] = Hyb[ii * HYW + jj] + CFLF * s4;
                }
            }
        }
    }
}

// ---------------------------------------------------------------------------
extern "C" void kernel_launch(void* const* d_in, const int* in_sizes, int n_in,
                              void* d_out, int out_size)
{
    const float* sb = (const float*)d_in[3];
    const float* sd = (const float*)d_in[4];
    const float* sg = (const float*)d_in[5];
    float* out = (float*)d_out;

    const float* e_base  = (const float*)d_in[0]; int e_off  = 0;
    const float* hx_base = (const float*)d_in[1]; int hx_off = 0;
    const float* hy_base = (const float*)d_in[2]; int hy_off = 0;

    const int STEP = BB * (EN + HXN + HYN);

    dim3 blk(32, 4, 1);
    dim3 gE(17, (1025 + 3) / 4, BB);   // 1025 row-pairs cover 2049 rows
    dim3 gF(17, 1024 / 4, BB);         // 1024 row-pairs cover 2048 rows

    for (int k = 0; k < 3; k++) {
        int eo_off  = k * STEP;
        int hxo_off = eo_off + BB * EN;
        int hyo_off = hxo_off + BB * HXN;

        k_amper<<<gE, blk>>>(e_base, e_off, hx_base, hx_off, hy_base, hy_off,
                             out, eo_off, sb, sd, sg);
        k_faraday<<<gF, blk>>>(out, eo_off, hx_base, hx_off, hy_base, hy_off,
                               out, hxo_off, hyo_off, sb, sd, sg);

        e_base = out;  e_off  = eo_off;
        hx_base = out; hx_off = hxo_off;
        hy_base = out; hy_off = hyo_off;
    }
}